// round 5
// baseline (speedup 1.0000x reference)
#include <cuda_runtime.h>

// BarlowTwinsLoss: e_q [16384,2048] f32, tau [16384,2048] f32, row-major.
// loss = sum_d (1 - clip(corr_d, -1+eps, 1-eps))^2, corr from column-normalized
// (ddof=1) features. Pure streaming reduction: 256 MB mandatory HBM reads.
//
// R5 (= R4 resubmitted after infra failure): single fused kernel, float4 loads
// (R1's 74.7%-DRAM pattern), NO __ldcs (measured -18us regression on sm_100a),
// last-block fp32 finalize. Deterministic: fixed-order sums, no float atomics.

#define NROWS 16384
#define NCOLS 2048
#define ROW_CHUNKS 8                                  // blockIdx.y
#define ROWS_PER_CHUNK (NROWS / ROW_CHUNKS)           // 2048
#define SUBCHUNKS 32                                  // threadIdx.y
#define ROWS_PER_THREAD (ROWS_PER_CHUNK / SUBCHUNKS)  // 64
#define XTHREADS 8                                    // float4 lanes -> 32 cols
#define COLS_PER_BLOCK (XTHREADS * 4)                 // 32
#define COL_BLOCKS (NCOLS / COLS_PER_BLOCK)           // 64
#define NBLOCKS (COL_BLOCKS * ROW_CHUNKS)             // 512

// 5 stats x 8 rowchunks x 2048 cols x 4B = 320 KB static scratch
__device__ float g_partial[5][ROW_CHUNKS][NCOLS];
__device__ unsigned int g_ticket;     // zero-init; reset by last block

__global__ void __launch_bounds__(256)
barlow_kernel(const float* __restrict__ e, const float* __restrict__ t,
              float* __restrict__ out)
{
    const int colbase = blockIdx.x * COLS_PER_BLOCK;
    const int col     = colbase + threadIdx.x * 4;
    const size_t row0 = (size_t)blockIdx.y * ROWS_PER_CHUNK
                      + (size_t)threadIdx.y * ROWS_PER_THREAD;

    const float4* __restrict__ e4 = (const float4*)(e + row0 * NCOLS + col);
    const float4* __restrict__ t4 = (const float4*)(t + row0 * NCOLS + col);
    const int rs4 = NCOLS / 4;        // float4 stride per row

    float se0=0.f,se1=0.f,se2=0.f,se3=0.f;
    float st0=0.f,st1=0.f,st2=0.f,st3=0.f;
    float ee0=0.f,ee1=0.f,ee2=0.f,ee3=0.f;
    float tt0=0.f,tt1=0.f,tt2=0.f,tt3=0.f;
    float et0=0.f,et1=0.f,et2=0.f,et3=0.f;

    #pragma unroll 4
    for (int r = 0; r < ROWS_PER_THREAD; ++r) {
        float4 a = e4[(size_t)r * rs4];
        float4 b = t4[(size_t)r * rs4];
        se0 += a.x; se1 += a.y; se2 += a.z; se3 += a.w;
        st0 += b.x; st1 += b.y; st2 += b.z; st3 += b.w;
        ee0 = fmaf(a.x,a.x,ee0); ee1 = fmaf(a.y,a.y,ee1);
        ee2 = fmaf(a.z,a.z,ee2); ee3 = fmaf(a.w,a.w,ee3);
        tt0 = fmaf(b.x,b.x,tt0); tt1 = fmaf(b.y,b.y,tt1);
        tt2 = fmaf(b.z,b.z,tt2); tt3 = fmaf(b.w,b.w,tt3);
        et0 = fmaf(a.x,b.x,et0); et1 = fmaf(a.y,b.y,et1);
        et2 = fmaf(a.z,b.z,et2); et3 = fmaf(a.w,b.w,et3);
    }

    // Shared: [stat][subchunk][col], padded row (33) -> conflict-free.
    __shared__ float sh[5][SUBCHUNKS][COLS_PER_BLOCK + 1];
    const int cx = threadIdx.x * 4;
    sh[0][threadIdx.y][cx+0]=se0; sh[0][threadIdx.y][cx+1]=se1;
    sh[0][threadIdx.y][cx+2]=se2; sh[0][threadIdx.y][cx+3]=se3;
    sh[1][threadIdx.y][cx+0]=st0; sh[1][threadIdx.y][cx+1]=st1;
    sh[1][threadIdx.y][cx+2]=st2; sh[1][threadIdx.y][cx+3]=st3;
    sh[2][threadIdx.y][cx+0]=ee0; sh[2][threadIdx.y][cx+1]=ee1;
    sh[2][threadIdx.y][cx+2]=ee2; sh[2][threadIdx.y][cx+3]=ee3;
    sh[3][threadIdx.y][cx+0]=tt0; sh[3][threadIdx.y][cx+1]=tt1;
    sh[3][threadIdx.y][cx+2]=tt2; sh[3][threadIdx.y][cx+3]=tt3;
    sh[4][threadIdx.y][cx+0]=et0; sh[4][threadIdx.y][cx+1]=et1;
    sh[4][threadIdx.y][cx+2]=et2; sh[4][threadIdx.y][cx+3]=et3;
    __syncthreads();

    const int tid = threadIdx.y * XTHREADS + threadIdx.x;

    // 160 threads: (stat s, col c). Fixed-order sum over 32 subchunks.
    if (tid < 5 * COLS_PER_BLOCK) {
        const int s = tid >> 5;
        const int c = tid & 31;
        float acc = 0.f;
        #pragma unroll
        for (int k = 0; k < SUBCHUNKS; ++k)
            acc += sh[s][k][c];
        g_partial[s][blockIdx.y][colbase + c] = acc;
    }

    // ---- last-block finalize -------------------------------------------
    __threadfence();                  // publish partials before the ticket
    __syncthreads();

    __shared__ unsigned int s_last;
    if (tid == 0)
        s_last = (atomicAdd(&g_ticket, 1u) == NBLOCKS - 1u) ? 1u : 0u;
    __syncthreads();
    if (!s_last) return;

    __threadfence();                  // acquire ordering for partial reads

    const float Nf   = 16384.0f;
    const float EPSf = 1e-9f;
    float loss = 0.f;

    for (int c0 = 0; c0 < NCOLS; c0 += 256) {
        const int ccol = c0 + tid;

        float S[5];
        #pragma unroll
        for (int s = 0; s < 5; ++s) {
            float acc = 0.f;
            #pragma unroll
            for (int rb = 0; rb < ROW_CHUNKS; ++rb)
                acc += g_partial[s][rb][ccol];
            S[s] = acc;
        }

        const float Se = S[0], St = S[1], See = S[2], Stt = S[3], Set = S[4];
        const float vare = (See - Se * Se / Nf) / (Nf - 1.0f);
        const float vart = (Stt - St * St / Nf) / (Nf - 1.0f);
        const float stde = fmaxf(sqrtf(fmaxf(vare, 0.f)), EPSf);
        const float stdt = fmaxf(sqrtf(fmaxf(vart, 0.f)), EPSf);
        const float cross = Set - Se * St / Nf;

        float c = cross / (stde * stdt) / (Nf + EPSf);
        c = fminf(fmaxf(c, -1.0f + EPSf), 1.0f - EPSf);
        const float d = 1.0f - c;
        loss = fmaf(d, d, loss);
    }

    __shared__ float red[256];
    red[tid] = loss;
    __syncthreads();
    #pragma unroll
    for (int s = 128; s > 0; s >>= 1) {
        if (tid < s) red[tid] += red[tid + s];
        __syncthreads();
    }
    if (tid == 0) {
        out[0] = red[0];
        g_ticket = 0;                 // reset for next graph replay
    }
}

// ---------------------------------------------------------------------------
extern "C" void kernel_launch(void* const* d_in, const int* in_sizes, int n_in,
                              void* d_out, int out_size)
{
    const float* e_q = (const float*)d_in[0];
    const float* tau = (const float*)d_in[1];
    float* out = (float*)d_out;

    dim3 block1(XTHREADS, SUBCHUNKS);        // 8 x 32 = 256
    dim3 grid1(COL_BLOCKS, ROW_CHUNKS);      // 64 x 8 = 512 blocks
    barlow_kernel<<<grid1, block1>>>(e_q, tau, out);
}

// round 7
// speedup vs baseline: 1.2196x; 1.2196x over previous
#include <cuda_runtime.h>

// BarlowTwinsLoss: e_q [16384,2048] f32, tau [16384,2048] f32, row-major.
// loss = sum_d (1 - clip(corr_d, -1+eps, 1-eps))^2 from column-normalized
// (ddof=1) features. Streaming reduction: 256 MB mandatory HBM reads.
//
// R7 (= R6 resubmitted after infra failure): stream kernel whose WARPS each
// cover 512B contiguous per load instr (R1's 74.7%-DRAM pattern; R5's
// warp-scattered float4 measured 50.9%). Intra-block reduce -> 1.25 MB
// partials; 8-block reduce+loss kernel (single-SM finalize over >1MB measured
// ~5us in R2, so the reduce is multi-block with its own ticket).

#define NROWS 16384
#define NCOLS 2048

// ---- stream kernel geometry ----
#define XT 32                                   // float4 lanes, x-fast
#define COLS_PER_BLOCK (XT * 4)                 // 128
#define YS 8                                    // row subchunks per block
#define COL_BLOCKS (NCOLS / COLS_PER_BLOCK)     // 16
#define ROW_CHUNKS 32                           // blockIdx.y
#define ROWS_PER_CHUNK (NROWS / ROW_CHUNKS)     // 512
#define ROWS_PER_THREAD (ROWS_PER_CHUNK / YS)   // 64

// ---- reduce kernel geometry ----
#define RBLOCKS 8
#define RTHREADS 256                            // 8*256 = 2048 = one per col

// partials: [stat][rowchunk][col], col contiguous -> coalesced reduce reads
__device__ float g_partial[5][ROW_CHUNKS][NCOLS];   // 1.25 MB
__device__ float g_lossp[RBLOCKS];
__device__ unsigned int g_ticket;                    // zero-init

// ---------------------------------------------------------------------------
// Kernel 1: streaming sufficient statistics.
// Warp = 32 consecutive float4 lanes -> 512B contiguous per load instruction.
// ---------------------------------------------------------------------------
__global__ void __launch_bounds__(XT * YS)
stats_kernel(const float* __restrict__ e, const float* __restrict__ t)
{
    const int colbase = blockIdx.x * COLS_PER_BLOCK;
    const int col     = colbase + threadIdx.x * 4;
    const size_t row0 = (size_t)blockIdx.y * ROWS_PER_CHUNK
                      + (size_t)threadIdx.y * ROWS_PER_THREAD;

    const float4* __restrict__ e4 = (const float4*)(e + row0 * NCOLS + col);
    const float4* __restrict__ t4 = (const float4*)(t + row0 * NCOLS + col);
    const int rs4 = NCOLS / 4;

    float se0=0.f,se1=0.f,se2=0.f,se3=0.f;
    float st0=0.f,st1=0.f,st2=0.f,st3=0.f;
    float ee0=0.f,ee1=0.f,ee2=0.f,ee3=0.f;
    float tt0=0.f,tt1=0.f,tt2=0.f,tt3=0.f;
    float et0=0.f,et1=0.f,et2=0.f,et3=0.f;

    #pragma unroll 4
    for (int r = 0; r < ROWS_PER_THREAD; ++r) {
        float4 a = e4[(size_t)r * rs4];
        float4 b = t4[(size_t)r * rs4];
        se0 += a.x; se1 += a.y; se2 += a.z; se3 += a.w;
        st0 += b.x; st1 += b.y; st2 += b.z; st3 += b.w;
        ee0 = fmaf(a.x,a.x,ee0); ee1 = fmaf(a.y,a.y,ee1);
        ee2 = fmaf(a.z,a.z,ee2); ee3 = fmaf(a.w,a.w,ee3);
        tt0 = fmaf(b.x,b.x,tt0); tt1 = fmaf(b.y,b.y,tt1);
        tt2 = fmaf(b.z,b.z,tt2); tt3 = fmaf(b.w,b.w,tt3);
        et0 = fmaf(a.x,b.x,et0); et1 = fmaf(a.y,b.y,et1);
        et2 = fmaf(a.z,b.z,et2); et3 = fmaf(a.w,b.w,et3);
    }

    __shared__ float sh[5][YS][COLS_PER_BLOCK + 4];
    const int cx = threadIdx.x * 4;
    sh[0][threadIdx.y][cx+0]=se0; sh[0][threadIdx.y][cx+1]=se1;
    sh[0][threadIdx.y][cx+2]=se2; sh[0][threadIdx.y][cx+3]=se3;
    sh[1][threadIdx.y][cx+0]=st0; sh[1][threadIdx.y][cx+1]=st1;
    sh[1][threadIdx.y][cx+2]=st2; sh[1][threadIdx.y][cx+3]=st3;
    sh[2][threadIdx.y][cx+0]=ee0; sh[2][threadIdx.y][cx+1]=ee1;
    sh[2][threadIdx.y][cx+2]=ee2; sh[2][threadIdx.y][cx+3]=ee3;
    sh[3][threadIdx.y][cx+0]=tt0; sh[3][threadIdx.y][cx+1]=tt1;
    sh[3][threadIdx.y][cx+2]=tt2; sh[3][threadIdx.y][cx+3]=tt3;
    sh[4][threadIdx.y][cx+0]=et0; sh[4][threadIdx.y][cx+1]=et1;
    sh[4][threadIdx.y][cx+2]=et2; sh[4][threadIdx.y][cx+3]=et3;
    __syncthreads();

    // 640 (stat,col) pairs reduced over 8 subchunks, fixed order.
    const int tid = threadIdx.y * XT + threadIdx.x;
    for (int i = tid; i < 5 * COLS_PER_BLOCK; i += XT * YS) {
        const int s = i / COLS_PER_BLOCK;
        const int c = i % COLS_PER_BLOCK;
        float acc = 0.f;
        #pragma unroll
        for (int k = 0; k < YS; ++k)
            acc += sh[s][k][c];
        g_partial[s][blockIdx.y][colbase + c] = acc;
    }
}

// ---------------------------------------------------------------------------
// Kernel 2: reduce + loss. 8 blocks x 256 threads, one thread per column.
// Coalesced reads (warp = 32 consecutive cols); fixed-order sums throughout.
// Last block (ticket) sums the 8 per-block loss partials.
// ---------------------------------------------------------------------------
__global__ void __launch_bounds__(RTHREADS)
loss_kernel(float* __restrict__ out)
{
    const int tid = threadIdx.x;
    const int col = blockIdx.x * RTHREADS + tid;

    float S[5];
    #pragma unroll
    for (int s = 0; s < 5; ++s) {
        float acc = 0.f;
        #pragma unroll
        for (int rb = 0; rb < ROW_CHUNKS; ++rb)
            acc += g_partial[s][rb][col];
        S[s] = acc;
    }

    const float Nf   = 16384.0f;
    const float EPSf = 1e-9f;
    const float Se = S[0], St = S[1], See = S[2], Stt = S[3], Set = S[4];
    const float vare = (See - Se * Se / Nf) / (Nf - 1.0f);
    const float vart = (Stt - St * St / Nf) / (Nf - 1.0f);
    const float stde = fmaxf(sqrtf(fmaxf(vare, 0.f)), EPSf);
    const float stdt = fmaxf(sqrtf(fmaxf(vart, 0.f)), EPSf);
    const float cross = Set - Se * St / Nf;

    float c = cross / (stde * stdt) / (Nf + EPSf);
    c = fminf(fmaxf(c, -1.0f + EPSf), 1.0f - EPSf);
    const float d = 1.0f - c;

    __shared__ float red[RTHREADS];
    red[tid] = d * d;
    __syncthreads();
    #pragma unroll
    for (int s = RTHREADS / 2; s > 0; s >>= 1) {
        if (tid < s) red[tid] += red[tid + s];
        __syncthreads();
    }
    if (tid == 0) g_lossp[blockIdx.x] = red[0];

    // ticket among the 8 reduce blocks; last one sums partial losses in order
    __threadfence();
    __syncthreads();
    __shared__ unsigned int s_last;
    if (tid == 0)
        s_last = (atomicAdd(&g_ticket, 1u) == RBLOCKS - 1u) ? 1u : 0u;
    __syncthreads();
    if (!s_last) return;
    __threadfence();

    if (tid == 0) {
        float loss = 0.f;
        #pragma unroll
        for (int b = 0; b < RBLOCKS; ++b)
            loss += g_lossp[b];
        out[0] = loss;
        g_ticket = 0;                 // reset for next graph replay
    }
}

// ---------------------------------------------------------------------------
extern "C" void kernel_launch(void* const* d_in, const int* in_sizes, int n_in,
                              void* d_out, int out_size)
{
    const float* e_q = (const float*)d_in[0];
    const float* tau = (const float*)d_in[1];
    float* out = (float*)d_out;

    dim3 block1(XT, YS);                         // 32 x 8 = 256
    dim3 grid1(COL_BLOCKS, ROW_CHUNKS);          // 16 x 32 = 512 blocks
    stats_kernel<<<grid1, block1>>>(e_q, tau);

    loss_kernel<<<RBLOCKS, RTHREADS>>>(out);
}

// round 9
// speedup vs baseline: 1.2640x; 1.0364x over previous
#include <cuda_runtime.h>

// BarlowTwinsLoss: e_q [16384,2048] f32, tau [16384,2048] f32, row-major.
// loss = sum_d (1 - clip(corr_d, -1+eps, 1-eps))^2 from column-normalized
// (ddof=1) features. Streaming reduction: 256 MB mandatory HBM reads.
//
// R8: stream kernel unchanged (warp = 512B contiguous per load instr; proved
// ~40us). Reduce kernel re-parallelized: R7's 8-block version was latency-
// bound (12.4us, occ 12.5%, 107GB/s); now 64 blocks x 256 threads with
// shared-memory rowchunk splitting -> 20 loads/thread, 64-SM MLP.

#define NROWS 16384
#define NCOLS 2048

// ---- stream kernel geometry ----
#define XT 32                                   // float4 lanes, x-fast
#define COLS_PER_BLOCK (XT * 4)                 // 128
#define YS 8                                    // row subchunks per block
#define COL_BLOCKS (NCOLS / COLS_PER_BLOCK)     // 16
#define ROW_CHUNKS 32                           // blockIdx.y
#define ROWS_PER_CHUNK (NROWS / ROW_CHUNKS)     // 512
#define ROWS_PER_THREAD (ROWS_PER_CHUNK / YS)   // 64

// ---- reduce kernel geometry ----
#define RBLOCKS 64                              // 64 blocks x 32 cols = 2048
#define RCOLS 32                                // cols per reduce block
#define RGROUPS 8                               // rowchunk groups (threadIdx.y)
#define RB_PER_GROUP (ROW_CHUNKS / RGROUPS)     // 4

// partials: [stat][rowchunk][col], col contiguous -> coalesced reduce reads
__device__ float g_partial[5][ROW_CHUNKS][NCOLS];   // 1.25 MB
__device__ float g_lossp[RBLOCKS];
__device__ unsigned int g_ticket;                    // zero-init

// ---------------------------------------------------------------------------
// Kernel 1: streaming sufficient statistics. (unchanged from R7)
// Warp = 32 consecutive float4 lanes -> 512B contiguous per load instruction.
// ---------------------------------------------------------------------------
__global__ void __launch_bounds__(XT * YS)
stats_kernel(const float* __restrict__ e, const float* __restrict__ t)
{
    const int colbase = blockIdx.x * COLS_PER_BLOCK;
    const int col     = colbase + threadIdx.x * 4;
    const size_t row0 = (size_t)blockIdx.y * ROWS_PER_CHUNK
                      + (size_t)threadIdx.y * ROWS_PER_THREAD;

    const float4* __restrict__ e4 = (const float4*)(e + row0 * NCOLS + col);
    const float4* __restrict__ t4 = (const float4*)(t + row0 * NCOLS + col);
    const int rs4 = NCOLS / 4;

    float se0=0.f,se1=0.f,se2=0.f,se3=0.f;
    float st0=0.f,st1=0.f,st2=0.f,st3=0.f;
    float ee0=0.f,ee1=0.f,ee2=0.f,ee3=0.f;
    float tt0=0.f,tt1=0.f,tt2=0.f,tt3=0.f;
    float et0=0.f,et1=0.f,et2=0.f,et3=0.f;

    #pragma unroll 4
    for (int r = 0; r < ROWS_PER_THREAD; ++r) {
        float4 a = e4[(size_t)r * rs4];
        float4 b = t4[(size_t)r * rs4];
        se0 += a.x; se1 += a.y; se2 += a.z; se3 += a.w;
        st0 += b.x; st1 += b.y; st2 += b.z; st3 += b.w;
        ee0 = fmaf(a.x,a.x,ee0); ee1 = fmaf(a.y,a.y,ee1);
        ee2 = fmaf(a.z,a.z,ee2); ee3 = fmaf(a.w,a.w,ee3);
        tt0 = fmaf(b.x,b.x,tt0); tt1 = fmaf(b.y,b.y,tt1);
        tt2 = fmaf(b.z,b.z,tt2); tt3 = fmaf(b.w,b.w,tt3);
        et0 = fmaf(a.x,b.x,et0); et1 = fmaf(a.y,b.y,et1);
        et2 = fmaf(a.z,b.z,et2); et3 = fmaf(a.w,b.w,et3);
    }

    __shared__ float sh[5][YS][COLS_PER_BLOCK + 4];
    const int cx = threadIdx.x * 4;
    sh[0][threadIdx.y][cx+0]=se0; sh[0][threadIdx.y][cx+1]=se1;
    sh[0][threadIdx.y][cx+2]=se2; sh[0][threadIdx.y][cx+3]=se3;
    sh[1][threadIdx.y][cx+0]=st0; sh[1][threadIdx.y][cx+1]=st1;
    sh[1][threadIdx.y][cx+2]=st2; sh[1][threadIdx.y][cx+3]=st3;
    sh[2][threadIdx.y][cx+0]=ee0; sh[2][threadIdx.y][cx+1]=ee1;
    sh[2][threadIdx.y][cx+2]=ee2; sh[2][threadIdx.y][cx+3]=ee3;
    sh[3][threadIdx.y][cx+0]=tt0; sh[3][threadIdx.y][cx+1]=tt1;
    sh[3][threadIdx.y][cx+2]=tt2; sh[3][threadIdx.y][cx+3]=tt3;
    sh[4][threadIdx.y][cx+0]=et0; sh[4][threadIdx.y][cx+1]=et1;
    sh[4][threadIdx.y][cx+2]=et2; sh[4][threadIdx.y][cx+3]=et3;
    __syncthreads();

    const int tid = threadIdx.y * XT + threadIdx.x;
    for (int i = tid; i < 5 * COLS_PER_BLOCK; i += XT * YS) {
        const int s = i / COLS_PER_BLOCK;
        const int c = i % COLS_PER_BLOCK;
        float acc = 0.f;
        #pragma unroll
        for (int k = 0; k < YS; ++k)
            acc += sh[s][k][c];
        g_partial[s][blockIdx.y][colbase + c] = acc;
    }
}

// ---------------------------------------------------------------------------
// Kernel 2: reduce + loss. 64 blocks x (32 cols x 8 rowchunk-groups).
// Each thread: 5 stats x 4 rowchunks = 20 coalesced loads. Shared combine
// over the 8 groups (fixed order), per-column loss, fixed-order tree reduce,
// ticketed final sum over 64 block losses. Fully deterministic.
// ---------------------------------------------------------------------------
__global__ void __launch_bounds__(RCOLS * RGROUPS)
loss_kernel(float* __restrict__ out)
{
    const int tx  = threadIdx.x;                 // col within block
    const int ty  = threadIdx.y;                 // rowchunk group
    const int col = blockIdx.x * RCOLS + tx;
    const int tid = ty * RCOLS + tx;

    // each thread sums its 4 rowchunks for all 5 stats
    float p[5];
    #pragma unroll
    for (int s = 0; s < 5; ++s) {
        float acc = 0.f;
        #pragma unroll
        for (int k = 0; k < RB_PER_GROUP; ++k)
            acc += g_partial[s][ty * RB_PER_GROUP + k][col];
        p[s] = acc;
    }

    __shared__ float sh[RGROUPS][5][RCOLS + 1];
    #pragma unroll
    for (int s = 0; s < 5; ++s)
        sh[ty][s][tx] = p[s];
    __syncthreads();

    __shared__ float red[RCOLS];
    if (ty == 0) {
        float S[5];
        #pragma unroll
        for (int s = 0; s < 5; ++s) {
            float acc = 0.f;
            #pragma unroll
            for (int g = 0; g < RGROUPS; ++g)   // fixed order
                acc += sh[g][s][tx];
            S[s] = acc;
        }

        const float Nf   = 16384.0f;
        const float EPSf = 1e-9f;
        const float Se = S[0], St = S[1], See = S[2], Stt = S[3], Set = S[4];
        const float vare = (See - Se * Se / Nf) / (Nf - 1.0f);
        const float vart = (Stt - St * St / Nf) / (Nf - 1.0f);
        const float stde = fmaxf(sqrtf(fmaxf(vare, 0.f)), EPSf);
        const float stdt = fmaxf(sqrtf(fmaxf(vart, 0.f)), EPSf);
        const float cross = Set - Se * St / Nf;

        float c = cross / (stde * stdt) / (Nf + EPSf);
        c = fminf(fmaxf(c, -1.0f + EPSf), 1.0f - EPSf);
        const float d = 1.0f - c;
        red[tx] = d * d;
    }
    __syncthreads();

    // fixed-order tree reduce of 32 per-column terms (ty==0 warp)
    if (ty == 0) {
        #pragma unroll
        for (int s = 16; s > 0; s >>= 1) {
            if (tx < s) red[tx] += red[tx + s];
            __syncwarp(0xFFFFFFFF);
        }
        if (tx == 0) g_lossp[blockIdx.x] = red[0];
    }

    // ticket among the 64 reduce blocks; last sums partials in index order
    __threadfence();
    __syncthreads();
    __shared__ unsigned int s_last;
    if (tid == 0)
        s_last = (atomicAdd(&g_ticket, 1u) == RBLOCKS - 1u) ? 1u : 0u;
    __syncthreads();
    if (!s_last) return;
    __threadfence();

    if (tid == 0) {
        float loss = 0.f;
        #pragma unroll
        for (int b = 0; b < RBLOCKS; ++b)
            loss += g_lossp[b];
        out[0] = loss;
        g_ticket = 0;                 // reset for next graph replay
    }
}

// ---------------------------------------------------------------------------
extern "C" void kernel_launch(void* const* d_in, const int* in_sizes, int n_in,
                              void* d_out, int out_size)
{
    const float* e_q = (const float*)d_in[0];
    const float* tau = (const float*)d_in[1];
    float* out = (float*)d_out;

    dim3 block1(XT, YS);                         // 32 x 8 = 256
    dim3 grid1(COL_BLOCKS, ROW_CHUNKS);          // 16 x 32 = 512 blocks
    stats_kernel<<<grid1, block1>>>(e_q, tau);

    dim3 block2(RCOLS, RGROUPS);                 // 32 x 8 = 256
    loss_kernel<<<RBLOCKS, block2>>>(out);
}